// round 1
// baseline (speedup 1.0000x reference)
#include <cuda_runtime.h>
#include <cstdint>

// Problem constants
#define BB      128
#define TOPK    32
#define MN      64
#define NODES   258        // MAX_NODES + 2
#define HDIM    128
#define EDIM    128
#define G3      384        // 3*H

// ---------------------------------------------------------------------------
// Device scratch (static allocation — no runtime allocs allowed)
// ---------------------------------------------------------------------------
__device__ float g_gi_rel[400 * G3];          // W_ih[:,E:] @ rel_table
__device__ float g_gi_ent[BB * TOPK * G3];    // W_ih[:,:E] @ ent + b_ih
__device__ float g_gh   [BB * NODES * G3];    // W_hh @ node_emb + b_hh
__device__ float g_upd  [BB * TOPK * HDIM];   // aggregated updates

// ---------------------------------------------------------------------------
// Helpers
// ---------------------------------------------------------------------------
__device__ __forceinline__ float fast_rcp(float x) {
    float r; asm("rcp.approx.f32 %0, %1;" : "=f"(r) : "f"(x)); return r;
}
__device__ __forceinline__ float sigmoid_f(float x) {
    return fast_rcp(1.0f + __expf(-x));
}
__device__ __forceinline__ float tanh_f(float x) {
    return fmaf(2.0f, sigmoid_f(2.0f * x), -1.0f);
}
__device__ __forceinline__ unsigned long long pack2(float x) {
    unsigned long long r;
    asm("mov.b64 %0, {%1, %1};" : "=l"(r) : "f"(x));
    return r;
}

// ---------------------------------------------------------------------------
// Kernel A: copy node_embeddings -> out (float4 vectorized)
// ---------------------------------------------------------------------------
__global__ void copy_kernel(const float4* __restrict__ in, float4* __restrict__ out, int n4) {
    for (int i = blockIdx.x * blockDim.x + threadIdx.x; i < n4; i += gridDim.x * blockDim.x)
        out[i] = in[i];
}

// ---------------------------------------------------------------------------
// Generic GEMM:  out[row, 0:384] = A[ridx(row), 0:128] @ W[:, woff:woff+128]^T + bias
//   A: K=128 rows gathered via optional index list
//   W: (384, ldw) row-major; uses columns [woff, woff+128)
// Tile: 64 rows x 384 cols per CTA, 256 threads, f32x2 packed FMA.
// ---------------------------------------------------------------------------
#define ASM_LD   65                      // padded ld for A^T in smem
#define WSM_LD   386                     // padded (even) ld for W^T in smem
#define GEMM_SMEM ((128 * ASM_LD + 128 * WSM_LD) * 4)

__global__ __launch_bounds__(256) void gemm384_kernel(
    const float* __restrict__ A, const int* __restrict__ gather, int nrows,
    const float* __restrict__ W, int ldw, int woff,
    const float* __restrict__ bias, float* __restrict__ out)
{
    extern __shared__ float sm[];
    float* Asm = sm;                 // [k][i]  stride ASM_LD
    float* Wsm = sm + 128 * ASM_LD;  // [k][g]  stride WSM_LD
    __shared__ int sh_ridx[64];

    const int tid  = threadIdx.x;
    const int row0 = blockIdx.x * 64;

    if (tid < 64) {
        int r = row0 + tid;
        sh_ridx[tid] = (r < nrows) ? (gather ? gather[r] : r) : -1;
    }
    __syncthreads();

    // Load A tile (transposed into smem), float4 global reads
    for (int idx = tid; idx < 64 * 32; idx += 256) {
        int i  = idx >> 5;
        int k4 = (idx & 31) * 4;
        int ridx = sh_ridx[i];
        float4 v = make_float4(0.f, 0.f, 0.f, 0.f);
        if (ridx >= 0)
            v = *reinterpret_cast<const float4*>(&A[(size_t)ridx * 128 + k4]);
        Asm[(k4 + 0) * ASM_LD + i] = v.x;
        Asm[(k4 + 1) * ASM_LD + i] = v.y;
        Asm[(k4 + 2) * ASM_LD + i] = v.z;
        Asm[(k4 + 3) * ASM_LD + i] = v.w;
    }
    // Load W tile (transposed), float4 global reads
    for (int idx = tid; idx < 384 * 32; idx += 256) {
        int g  = idx >> 5;
        int k4 = (idx & 31) * 4;
        float4 v = *reinterpret_cast<const float4*>(&W[(size_t)g * ldw + woff + k4]);
        Wsm[(k4 + 0) * WSM_LD + g] = v.x;
        Wsm[(k4 + 1) * WSM_LD + g] = v.y;
        Wsm[(k4 + 2) * WSM_LD + g] = v.z;
        Wsm[(k4 + 3) * WSM_LD + g] = v.w;
    }
    __syncthreads();

    const int ty = tid >> 5;   // 0..7   rows ty*8 .. ty*8+7
    const int tx = tid & 31;   // cols: 64*j + 2*tx (j=0..5)

    unsigned long long acc[8][6];
#pragma unroll
    for (int r = 0; r < 8; r++)
#pragma unroll
        for (int j = 0; j < 6; j++) acc[r][j] = 0ull;

#pragma unroll 2
    for (int k = 0; k < 128; k++) {
        unsigned long long av[8];
#pragma unroll
        for (int r = 0; r < 8; r++)
            av[r] = pack2(Asm[k * ASM_LD + ty * 8 + r]);
        unsigned long long wv[6];
#pragma unroll
        for (int j = 0; j < 6; j++)
            wv[j] = *reinterpret_cast<const unsigned long long*>(
                        &Wsm[k * WSM_LD + j * 64 + 2 * tx]);
#pragma unroll
        for (int r = 0; r < 8; r++)
#pragma unroll
            for (int j = 0; j < 6; j++)
                asm("fma.rn.f32x2 %0, %1, %2, %0;"
                    : "+l"(acc[r][j]) : "l"(av[r]), "l"(wv[j]));
    }

#pragma unroll
    for (int r = 0; r < 8; r++) {
        int row = row0 + ty * 8 + r;
        if (row >= nrows) continue;
#pragma unroll
        for (int j = 0; j < 6; j++) {
            int col = j * 64 + 2 * tx;
            float lo, hi;
            asm("mov.b64 {%0, %1}, %2;" : "=f"(lo), "=f"(hi) : "l"(acc[r][j]));
            if (bias) {
                float2 bv = *reinterpret_cast<const float2*>(&bias[col]);
                lo += bv.x; hi += bv.y;
            }
            *reinterpret_cast<float2*>(&out[(size_t)row * G3 + col]) =
                make_float2(lo, hi);
        }
    }
}

// ---------------------------------------------------------------------------
// Kernel E: per (b, 32-channel chunk) GRU aggregation.
//   smem caches gh-slice (258x96), h-slice (258x32), gi_ent-slice (32x96),
//   neighbor list (32x64 int2), neighbor counts.
// ---------------------------------------------------------------------------
#define OFF_GH   0
#define OFF_H    (258 * 96 * 4)                 //  99072
#define OFF_GI   (OFF_H + 258 * 32 * 4)          // 132096
#define OFF_NB   (OFF_GI + 32 * 96 * 4)          // 144384
#define OFF_NUM  (OFF_NB + 32 * 64 * 8)          // 160768
#define AGG_SMEM (OFF_NUM + 32 * 4)              // 160896

__global__ __launch_bounds__(512) void aggregate_kernel(
    const float* __restrict__ node_emb,
    const float* __restrict__ gi_rel,
    const float* __restrict__ gi_ent,
    const float* __restrict__ gh_all,
    const int2*  __restrict__ neighbors,
    const int*   __restrict__ nb_num,
    float* __restrict__ upd)
{
    extern __shared__ char smraw[];
    float* sh_gh  = reinterpret_cast<float*>(smraw + OFF_GH);   // [n][gate][32]
    float* sh_h   = reinterpret_cast<float*>(smraw + OFF_H);    // [n][32]
    float* sh_gi  = reinterpret_cast<float*>(smraw + OFF_GI);   // [t][gate][32]
    int2*  sh_nb  = reinterpret_cast<int2*>(smraw + OFF_NB);    // [t][m]
    int*   sh_num = reinterpret_cast<int*>(smraw + OFF_NUM);    // [t]

    const int tid = threadIdx.x;
    const int c   = blockIdx.x;        // channel chunk 0..3
    const int b   = blockIdx.y;        // batch
    const int cc0 = c * 32;

    // Fill gh slice: 258 nodes * 3 gates * 8 float4
    for (int idx = tid; idx < 258 * 24; idx += 512) {
        int n = idx / 24, q = idx % 24;
        int gate = q >> 3, jj = (q & 7) * 4;
        float4 v = *reinterpret_cast<const float4*>(
            &gh_all[((size_t)b * NODES + n) * G3 + gate * 128 + cc0 + jj]);
        *reinterpret_cast<float4*>(&sh_gh[(n * 3 + gate) * 32 + jj]) = v;
    }
    // Fill h slice
    for (int idx = tid; idx < 258 * 8; idx += 512) {
        int n = idx >> 3, jj = (idx & 7) * 4;
        float4 v = *reinterpret_cast<const float4*>(
            &node_emb[((size_t)b * NODES + n) * HDIM + cc0 + jj]);
        *reinterpret_cast<float4*>(&sh_h[n * 32 + jj]) = v;
    }
    // Fill gi_ent slice
    for (int idx = tid; idx < 32 * 24; idx += 512) {
        int t = idx / 24, q = idx % 24;
        int gate = q >> 3, jj = (q & 7) * 4;
        float4 v = *reinterpret_cast<const float4*>(
            &gi_ent[((size_t)b * TOPK + t) * G3 + gate * 128 + cc0 + jj]);
        *reinterpret_cast<float4*>(&sh_gi[(t * 3 + gate) * 32 + jj]) = v;
    }
    // Neighbor list + counts
    for (int idx = tid; idx < TOPK * MN; idx += 512)
        sh_nb[idx] = neighbors[(size_t)b * TOPK * MN + idx];
    if (tid < TOPK)
        sh_num[tid] = nb_num[b * TOPK + tid];
    __syncthreads();

    const int warp = tid >> 5;
    const int lane = tid & 31;

    for (int t = warp; t < TOPK; t += 16) {
        const float gir = sh_gi[(t * 3 + 0) * 32 + lane];
        const float giz = sh_gi[(t * 3 + 1) * 32 + lane];
        const float gin = sh_gi[(t * 3 + 2) * 32 + lane];
        const int   num = sh_num[t];

        float acc = 0.f;
        for (int m = 0; m < num; m++) {
            int2 nb = sh_nb[t * MN + m];           // broadcast LDS.64
            const int node = nb.x, rel = nb.y;
            const float* gr = gi_rel + (size_t)rel * G3 + cc0 + lane;
            const float* gh = sh_gh + node * 96 + lane;
            const float  h  = sh_h[node * 32 + lane];

            float r = sigmoid_f(gir + gr[0]   + gh[0]);
            float z = sigmoid_f(giz + gr[128] + gh[32]);
            float n = tanh_f   (gin + gr[256] + fmaf(r, gh[64], 0.f) + (r - 1.f) * 0.f
                                 + r * 0.f + (r * gh[64] - r * gh[64]));
            // n = tanh(gi_n + gr_n + r * gh_n)   (gh_n includes b_hh, per GRUCell)
            n = tanh_f(gin + gr[256] + r * gh[64]);
            acc += fmaf(z, h - n, n);              // (1-z)*n + z*h
        }
        float u = (num > 0) ? acc / (float)num : 0.f;
        upd[((size_t)b * TOPK + t) * HDIM + cc0 + lane] = u;
    }
}

// ---------------------------------------------------------------------------
// Kernel F: scatter updates (last occurrence of duplicate aim_node wins,
// matching sequential XLA scatter order)
// ---------------------------------------------------------------------------
__global__ void scatter_kernel(const int* __restrict__ aim_nodes,
                               const float* __restrict__ upd,
                               float* __restrict__ out)
{
    const int t = blockIdx.x, b = blockIdx.y;
    const int node = aim_nodes[b * TOPK + t];
    __shared__ int dup;
    if (threadIdx.x == 0) {
        int d = 0;
        for (int t2 = t + 1; t2 < TOPK; t2++)
            d |= (aim_nodes[b * TOPK + t2] == node);
        dup = d;
    }
    __syncthreads();
    if (!dup)
        out[((size_t)b * NODES + node) * HDIM + threadIdx.x] =
            upd[((size_t)b * TOPK + t) * HDIM + threadIdx.x];
}

// ---------------------------------------------------------------------------
// Host launcher
// ---------------------------------------------------------------------------
extern "C" void kernel_launch(void* const* d_in, const int* in_sizes, int n_in,
                              void* d_out, int out_size)
{
    const float* node_emb = (const float*)d_in[0];
    const float* ent_tab  = (const float*)d_in[1];
    const float* rel_tab  = (const float*)d_in[2];
    const float* W_ih     = (const float*)d_in[3];
    const float* W_hh     = (const float*)d_in[4];
    const float* b_ih     = (const float*)d_in[5];
    const float* b_hh     = (const float*)d_in[6];
    const int*   aim_nd   = (const int*)d_in[7];
    const int*   aim_ent  = (const int*)d_in[8];
    const int*   nbrs     = (const int*)d_in[9];
    const int*   nb_num   = (const int*)d_in[10];
    float* out = (float*)d_out;

    float *p_gi_rel, *p_gi_ent, *p_gh, *p_upd;
    cudaGetSymbolAddress((void**)&p_gi_rel, g_gi_rel);
    cudaGetSymbolAddress((void**)&p_gi_ent, g_gi_ent);
    cudaGetSymbolAddress((void**)&p_gh,     g_gh);
    cudaGetSymbolAddress((void**)&p_upd,    g_upd);

    cudaFuncSetAttribute(gemm384_kernel,
        cudaFuncAttributeMaxDynamicSharedMemorySize, GEMM_SMEM);
    cudaFuncSetAttribute(aggregate_kernel,
        cudaFuncAttributeMaxDynamicSharedMemorySize, AGG_SMEM);

    // 1) copy base embeddings to output
    const int n4 = (BB * NODES * HDIM) / 4;
    copy_kernel<<<2048, 256>>>((const float4*)node_emb, (float4*)out, n4);

    // 2) gi_rel = rel_table @ W_ih[:,E:2E]^T          (400 x 384)
    gemm384_kernel<<<7, 256, GEMM_SMEM>>>(
        rel_tab, nullptr, 400, W_ih, 256, 128, nullptr, p_gi_rel);

    // 3) gi_ent = ent_table[aim_entities] @ W_ih[:,0:E]^T + b_ih   (4096 x 384)
    gemm384_kernel<<<64, 256, GEMM_SMEM>>>(
        ent_tab, aim_ent, BB * TOPK, W_ih, 256, 0, b_ih, p_gi_ent);

    // 4) gh = node_embeddings @ W_hh^T + b_hh          (33024 x 384)
    gemm384_kernel<<<516, 256, GEMM_SMEM>>>(
        node_emb, nullptr, BB * NODES, W_hh, 128, 0, b_hh, p_gh);

    // 5) GRU + masked mean aggregation
    aggregate_kernel<<<dim3(4, BB), 512, AGG_SMEM>>>(
        node_emb, p_gi_rel, p_gi_ent, p_gh,
        (const int2*)nbrs, nb_num, p_upd);

    // 6) scatter updated rows (last-wins on duplicate aim nodes)
    scatter_kernel<<<dim3(TOPK, BB), 128>>>(aim_nd, p_upd, out);
}

// round 3
// speedup vs baseline: 1.4743x; 1.4743x over previous
#include <cuda_runtime.h>
#include <cstdint>

// Problem constants
#define BB      128
#define TOPK    32
#define MN      64
#define NODES   258        // MAX_NODES + 2
#define HDIM    128
#define G3      384        // 3*H

// ---------------------------------------------------------------------------
// Device scratch
// ---------------------------------------------------------------------------
__device__ float g_gi_rel[400 * G3];
__device__ float g_gi_ent[BB * TOPK * G3];
__device__ float g_gh   [BB * NODES * G3];
__device__ float g_upd  [BB * TOPK * HDIM];

// ---------------------------------------------------------------------------
// Helpers
// ---------------------------------------------------------------------------
__device__ __forceinline__ float fast_rcp(float x) {
    float r; asm("rcp.approx.f32 %0, %1;" : "=f"(r) : "f"(x)); return r;
}
__device__ __forceinline__ float sigmoid_f(float x) { return fast_rcp(1.0f + __expf(-x)); }
__device__ __forceinline__ float tanh_f(float x)    { return fmaf(2.0f, sigmoid_f(2.0f * x), -1.0f); }

__device__ __forceinline__ uint32_t f2tf32(float f) {
    uint32_t u;
    asm("cvt.rna.tf32.f32 %0, %1;" : "=r"(u) : "f"(f));
    return u;
}
__device__ __forceinline__ void mma_tf32(float* d, const uint32_t* a, const uint32_t* b) {
    asm volatile(
        "mma.sync.aligned.m16n8k8.row.col.f32.tf32.tf32.f32 "
        "{%0,%1,%2,%3}, {%4,%5,%6,%7}, {%8,%9}, {%0,%1,%2,%3};"
        : "+f"(d[0]), "+f"(d[1]), "+f"(d[2]), "+f"(d[3])
        : "r"(a[0]), "r"(a[1]), "r"(a[2]), "r"(a[3]), "r"(b[0]), "r"(b[1]));
}

// ---------------------------------------------------------------------------
// Kernel A: copy node_embeddings -> out
// ---------------------------------------------------------------------------
__global__ void copy_kernel(const float4* __restrict__ in, float4* __restrict__ out, int n4) {
    for (int i = blockIdx.x * blockDim.x + threadIdx.x; i < n4; i += gridDim.x * blockDim.x)
        out[i] = in[i];
}

// ---------------------------------------------------------------------------
// Fused tf32 mma.sync GEMM: 128x128 output tile per CTA, 3 sub-problems
// routed by blockIdx.x:
//   [0,774):   gh     = node_emb(33024x128) @ W_hh^T            + b_hh
//   [774,870): gi_ent = ent_tab[aim_ent](4096x128) @ W_ih[:,:128]^T + b_ih
//   [870,882): gi_rel = rel_tab(400x128) @ W_ih[:,128:256]^T     (no bias)
// ---------------------------------------------------------------------------
#define APITCH 132
#define OFFA    0
#define OFFB    (128 * APITCH * 4)              //  67584
#define OFFBIAS (OFFB + 128 * APITCH * 4)       // 135168
#define OFFRIDX (OFFBIAS + 128 * 4)             // 135680
#define GEMM_SMEM (OFFRIDX + 128 * 4)           // 136192

__global__ __launch_bounds__(256) void gemm_mma_kernel(
    const float* __restrict__ node_emb,
    const float* __restrict__ ent_tab,
    const float* __restrict__ rel_tab,
    const float* __restrict__ W_ih,
    const float* __restrict__ W_hh,
    const float* __restrict__ b_ih,
    const float* __restrict__ b_hh,
    const int*   __restrict__ aim_ent,
    float* __restrict__ out_gh,
    float* __restrict__ out_gi_ent,
    float* __restrict__ out_gi_rel)
{
    extern __shared__ char sm[];
    uint32_t* As = reinterpret_cast<uint32_t*>(sm + OFFA);     // [row][k] pitch 132
    uint32_t* Bs = reinterpret_cast<uint32_t*>(sm + OFFB);     // [n][k]   pitch 132
    float*    sh_bias = reinterpret_cast<float*>(sm + OFFBIAS);
    int*      sh_ridx = reinterpret_cast<int*>(sm + OFFRIDX);

    const int tid  = threadIdx.x;
    const int wid  = tid >> 5;
    const int lane = tid & 31;

    // ---- routing ----
    int bx = blockIdx.x;
    const float* A; const int* gather = nullptr; int nrows;
    const float* W; int ldw, woff; const float* bias; float* out;
    int tile, gate;
    if (bx < 774) {
        tile = bx / 3; gate = bx % 3;
        A = node_emb; nrows = BB * NODES;
        W = W_hh; ldw = 128; woff = 0; bias = b_hh; out = out_gh;
    } else if (bx < 870) {
        int i = bx - 774; tile = i / 3; gate = i % 3;
        A = ent_tab; gather = aim_ent; nrows = BB * TOPK;
        W = W_ih; ldw = 256; woff = 0; bias = b_ih; out = out_gi_ent;
    } else {
        int i = bx - 870; tile = i / 3; gate = i % 3;
        A = rel_tab; nrows = 400;
        W = W_ih; ldw = 256; woff = 128; bias = nullptr; out = out_gi_rel;
    }
    const int row0 = tile * 128;

    if (tid < 128) {
        int r = row0 + tid;
        sh_ridx[tid] = (r < nrows) ? (gather ? gather[r] : r) : -1;
        sh_bias[tid] = bias ? bias[gate * 128 + tid] : 0.0f;
    }
    __syncthreads();

    // ---- fill A tile (tf32-converted), pitch 132 ----
    for (int idx = tid; idx < 128 * 32; idx += 256) {
        int i  = idx >> 5;
        int k4 = (idx & 31) << 2;
        int ridx = sh_ridx[i];
        float4 v = make_float4(0.f, 0.f, 0.f, 0.f);
        if (ridx >= 0)
            v = *reinterpret_cast<const float4*>(&A[(size_t)ridx * 128 + k4]);
        uint32_t* p = &As[i * APITCH + k4];
        p[0] = f2tf32(v.x); p[1] = f2tf32(v.y); p[2] = f2tf32(v.z); p[3] = f2tf32(v.w);
    }
    // ---- fill B tile: Bs[n][k] = W[gate*128+n][woff+k] ----
    for (int idx = tid; idx < 128 * 32; idx += 256) {
        int n  = idx >> 5;
        int k4 = (idx & 31) << 2;
        float4 v = *reinterpret_cast<const float4*>(&W[(size_t)(gate * 128 + n) * ldw + woff + k4]);
        uint32_t* p = &Bs[n * APITCH + k4];
        p[0] = f2tf32(v.x); p[1] = f2tf32(v.y); p[2] = f2tf32(v.z); p[3] = f2tf32(v.w);
    }
    __syncthreads();

    // ---- warp MMA: 8 warps = 2(row) x 4(col); each 64 rows x 32 cols ----
    const int quad  = lane >> 2;        // 0..7
    const int tq    = lane & 3;         // 0..3
    const int rbase = (wid >> 2) * 64;  // 0 or 64
    const int cbase = (wid & 3) * 32;   // 0,32,64,96

    float acc[4][4][4];
#pragma unroll
    for (int mt = 0; mt < 4; mt++)
#pragma unroll
        for (int nt = 0; nt < 4; nt++)
#pragma unroll
            for (int r = 0; r < 4; r++) acc[mt][nt][r] = 0.f;

#pragma unroll
    for (int ks = 0; ks < 16; ks++) {
        const int k0 = ks * 8;
        uint32_t af[4][4];
#pragma unroll
        for (int mt = 0; mt < 4; mt++) {
            int r = rbase + mt * 16 + quad;
            af[mt][0] = As[r * APITCH + k0 + tq];
            af[mt][1] = As[(r + 8) * APITCH + k0 + tq];
            af[mt][2] = As[r * APITCH + k0 + tq + 4];
            af[mt][3] = As[(r + 8) * APITCH + k0 + tq + 4];
        }
        uint32_t bf[4][2];
#pragma unroll
        for (int nt = 0; nt < 4; nt++) {
            int c = cbase + nt * 8 + quad;
            bf[nt][0] = Bs[c * APITCH + k0 + tq];
            bf[nt][1] = Bs[c * APITCH + k0 + tq + 4];
        }
#pragma unroll
        for (int mt = 0; mt < 4; mt++)
#pragma unroll
            for (int nt = 0; nt < 4; nt++)
                mma_tf32(acc[mt][nt], af[mt], bf[nt]);
    }

    // ---- epilogue: add bias, store float2 ----
#pragma unroll
    for (int mt = 0; mt < 4; mt++) {
#pragma unroll
        for (int nt = 0; nt < 4; nt++) {
            const int col = cbase + nt * 8 + tq * 2;           // within gate chunk
            const float b0 = sh_bias[col], b1 = sh_bias[col + 1];
            const int row = row0 + rbase + mt * 16 + quad;
            if (row < nrows)
                *reinterpret_cast<float2*>(&out[(size_t)row * G3 + gate * 128 + col]) =
                    make_float2(acc[mt][nt][0] + b0, acc[mt][nt][1] + b1);
            if (row + 8 < nrows)
                *reinterpret_cast<float2*>(&out[(size_t)(row + 8) * G3 + gate * 128 + col]) =
                    make_float2(acc[mt][nt][2] + b0, acc[mt][nt][3] + b1);
        }
    }
}

// ---------------------------------------------------------------------------
// GRU aggregation per (batch, 32-channel chunk)
// ---------------------------------------------------------------------------
#define OFF_GH   0
#define OFF_H    (258 * 96 * 4)
#define OFF_GI   (OFF_H + 258 * 32 * 4)
#define OFF_NB   (OFF_GI + 32 * 96 * 4)
#define OFF_NUM  (OFF_NB + 32 * 64 * 8)
#define AGG_SMEM (OFF_NUM + 32 * 4)

__global__ __launch_bounds__(512) void aggregate_kernel(
    const float* __restrict__ node_emb,
    const float* __restrict__ gi_rel,
    const float* __restrict__ gi_ent,
    const float* __restrict__ gh_all,
    const int2*  __restrict__ neighbors,
    const int*   __restrict__ nb_num,
    float* __restrict__ upd)
{
    extern __shared__ char smraw[];
    float* sh_gh  = reinterpret_cast<float*>(smraw + OFF_GH);
    float* sh_h   = reinterpret_cast<float*>(smraw + OFF_H);
    float* sh_gi  = reinterpret_cast<float*>(smraw + OFF_GI);
    int2*  sh_nb  = reinterpret_cast<int2*>(smraw + OFF_NB);
    int*   sh_num = reinterpret_cast<int*>(smraw + OFF_NUM);

    const int tid = threadIdx.x;
    const int c   = blockIdx.x;
    const int b   = blockIdx.y;
    const int cc0 = c * 32;

    for (int idx = tid; idx < 258 * 24; idx += 512) {
        int n = idx / 24, q = idx % 24;
        int gate = q >> 3, jj = (q & 7) * 4;
        float4 v = *reinterpret_cast<const float4*>(
            &gh_all[((size_t)b * NODES + n) * G3 + gate * 128 + cc0 + jj]);
        *reinterpret_cast<float4*>(&sh_gh[(n * 3 + gate) * 32 + jj]) = v;
    }
    for (int idx = tid; idx < 258 * 8; idx += 512) {
        int n = idx >> 3, jj = (idx & 7) * 4;
        float4 v = *reinterpret_cast<const float4*>(
            &node_emb[((size_t)b * NODES + n) * HDIM + cc0 + jj]);
        *reinterpret_cast<float4*>(&sh_h[n * 32 + jj]) = v;
    }
    for (int idx = tid; idx < 32 * 24; idx += 512) {
        int t = idx / 24, q = idx % 24;
        int gate = q >> 3, jj = (q & 7) * 4;
        float4 v = *reinterpret_cast<const float4*>(
            &gi_ent[((size_t)b * TOPK + t) * G3 + gate * 128 + cc0 + jj]);
        *reinterpret_cast<float4*>(&sh_gi[(t * 3 + gate) * 32 + jj]) = v;
    }
    for (int idx = tid; idx < TOPK * MN; idx += 512)
        sh_nb[idx] = neighbors[(size_t)b * TOPK * MN + idx];
    if (tid < TOPK)
        sh_num[tid] = nb_num[b * TOPK + tid];
    __syncthreads();

    const int warp = tid >> 5;
    const int lane = tid & 31;

    for (int t = warp; t < TOPK; t += 16) {
        const float gir = sh_gi[(t * 3 + 0) * 32 + lane];
        const float giz = sh_gi[(t * 3 + 1) * 32 + lane];
        const float gin = sh_gi[(t * 3 + 2) * 32 + lane];
        const int   num = sh_num[t];

        int   node = 0;
        float a0 = 0.f, a1 = 0.f, a2 = 0.f;
        if (num > 0) {
            int2 nb = sh_nb[t * MN];
            node = nb.x;
            const float* gr = gi_rel + (size_t)nb.y * G3 + cc0 + lane;
            a0 = gr[0]; a1 = gr[128]; a2 = gr[256];
        }

        float acc = 0.f;
        for (int m = 0; m < num; m++) {
            const int   cnode = node;
            const float c0 = a0, c1 = a1, c2 = a2;
            if (m + 1 < num) {
                int2 nb = sh_nb[t * MN + m + 1];
                node = nb.x;
                const float* gr = gi_rel + (size_t)nb.y * G3 + cc0 + lane;
                a0 = gr[0]; a1 = gr[128]; a2 = gr[256];
            }
            const float* gh = sh_gh + cnode * 96 + lane;
            const float  h  = sh_h[cnode * 32 + lane];

            float r = sigmoid_f(gir + c0 + gh[0]);
            float z = sigmoid_f(giz + c1 + gh[32]);
            float n = tanh_f   (gin + c2 + r * gh[64]);
            acc += fmaf(z, h - n, n);
        }
        float u = (num > 0) ? acc / (float)num : 0.f;
        upd[((size_t)b * TOPK + t) * HDIM + cc0 + lane] = u;
    }
}

// ---------------------------------------------------------------------------
// scatter (last-wins on duplicate aim_nodes)
// ---------------------------------------------------------------------------
__global__ void scatter_kernel(const int* __restrict__ aim_nodes,
                               const float* __restrict__ upd,
                               float* __restrict__ out)
{
    const int t = blockIdx.x, b = blockIdx.y;
    const int node = aim_nodes[b * TOPK + t];
    __shared__ int dup;
    if (threadIdx.x == 0) {
        int d = 0;
        for (int t2 = t + 1; t2 < TOPK; t2++)
            d |= (aim_nodes[b * TOPK + t2] == node);
        dup = d;
    }
    __syncthreads();
    if (!dup)
        out[((size_t)b * NODES + node) * HDIM + threadIdx.x] =
            upd[((size_t)b * TOPK + t) * HDIM + threadIdx.x];
}

// ---------------------------------------------------------------------------
// Host launcher
// ---------------------------------------------------------------------------
extern "C" void kernel_launch(void* const* d_in, const int* in_sizes, int n_in,
                              void* d_out, int out_size)
{
    const float* node_emb = (const float*)d_in[0];
    const float* ent_tab  = (const float*)d_in[1];
    const float* rel_tab  = (const float*)d_in[2];
    const float* W_ih     = (const float*)d_in[3];
    const float* W_hh     = (const float*)d_in[4];
    const float* b_ih     = (const float*)d_in[5];
    const float* b_hh     = (const float*)d_in[6];
    const int*   aim_nd   = (const int*)d_in[7];
    const int*   aim_ent  = (const int*)d_in[8];
    const int*   nbrs     = (const int*)d_in[9];
    const int*   nb_num   = (const int*)d_in[10];
    float* out = (float*)d_out;

    float *p_gi_rel, *p_gi_ent, *p_gh, *p_upd;
    cudaGetSymbolAddress((void**)&p_gi_rel, g_gi_rel);
    cudaGetSymbolAddress((void**)&p_gi_ent, g_gi_ent);
    cudaGetSymbolAddress((void**)&p_gh,     g_gh);
    cudaGetSymbolAddress((void**)&p_upd,    g_upd);

    cudaFuncSetAttribute(gemm_mma_kernel,
        cudaFuncAttributeMaxDynamicSharedMemorySize, GEMM_SMEM);
    cudaFuncSetAttribute(aggregate_kernel,
        cudaFuncAttributeMaxDynamicSharedMemorySize, AGG_SMEM);

    // 1) copy base embeddings to output
    const int n4 = (BB * NODES * HDIM) / 4;
    copy_kernel<<<2048, 256>>>((const float4*)node_emb, (float4*)out, n4);

    // 2-4) all three GEMMs fused into one launch (882 CTAs)
    gemm_mma_kernel<<<882, 256, GEMM_SMEM>>>(
        node_emb, ent_tab, rel_tab, W_ih, W_hh, b_ih, b_hh, aim_ent,
        p_gh, p_gi_ent, p_gi_rel);

    // 5) GRU + masked mean aggregation
    aggregate_kernel<<<dim3(4, BB), 512, AGG_SMEM>>>(
        node_emb, p_gi_rel, p_gi_ent, p_gh,
        (const int2*)nbrs, nb_num, p_upd);

    // 6) scatter updated rows
    scatter_kernel<<<dim3(TOPK, BB), 128>>>(aim_nd, p_upd, out);
}

// round 4
// speedup vs baseline: 1.5404x; 1.0448x over previous
#include <cuda_runtime.h>
#include <cstdint>

// Problem constants
#define BB      128
#define TOPK    32
#define MN      64
#define NODES   258        // MAX_NODES + 2
#define HDIM    128
#define G3      384        // 3*H

// ---------------------------------------------------------------------------
// Device scratch
// ---------------------------------------------------------------------------
__device__ float g_gi_rel[400 * G3];
__device__ float g_gi_ent[BB * TOPK * G3];
__device__ float g_gh   [BB * NODES * G3];
__device__ int   g_win  [BB * TOPK];          // aim node if winner, else -1

// ---------------------------------------------------------------------------
// Helpers
// ---------------------------------------------------------------------------
__device__ __forceinline__ float tanh_ap(float x) {
    float y; asm("tanh.approx.f32 %0, %1;" : "=f"(y) : "f"(x)); return y;
}
__device__ __forceinline__ float sigmoid_t(float x) {
    return fmaf(0.5f, tanh_ap(0.5f * x), 0.5f);
}
__device__ __forceinline__ uint32_t f2tf32(float f) {
    uint32_t u;
    asm("cvt.rna.tf32.f32 %0, %1;" : "=r"(u) : "f"(f));
    return u;
}
__device__ __forceinline__ void mma_tf32(float* d, const uint32_t* a, const uint32_t* b) {
    asm volatile(
        "mma.sync.aligned.m16n8k8.row.col.f32.tf32.tf32.f32 "
        "{%0,%1,%2,%3}, {%4,%5,%6,%7}, {%8,%9}, {%0,%1,%2,%3};"
        : "+f"(d[0]), "+f"(d[1]), "+f"(d[2]), "+f"(d[3])
        : "r"(a[0]), "r"(a[1]), "r"(a[2]), "r"(a[3]), "r"(b[0]), "r"(b[1]));
}

// ---------------------------------------------------------------------------
// Kernel 1: copy node_embeddings -> out
// ---------------------------------------------------------------------------
__global__ void copy_kernel(const float4* __restrict__ in, float4* __restrict__ out, int n4) {
    for (int i = blockIdx.x * blockDim.x + threadIdx.x; i < n4; i += gridDim.x * blockDim.x)
        out[i] = in[i];
}

// ---------------------------------------------------------------------------
// Kernel 2: fused tf32 mma.sync GEMM (882 CTAs, routed by blockIdx.x)
//   [0,774):   gh     = node_emb(33024x128) @ W_hh^T             + b_hh
//   [774,870): gi_ent = ent_tab[aim_ent](4096x128) @ W_ih[:,:128]^T + b_ih
//   [870,882): gi_rel = rel_tab(400x128) @ W_ih[:,128:256]^T      (no bias)
// ---------------------------------------------------------------------------
#define APITCH 132
#define OFFA    0
#define OFFB    (128 * APITCH * 4)
#define OFFBIAS (OFFB + 128 * APITCH * 4)
#define OFFRIDX (OFFBIAS + 128 * 4)
#define GEMM_SMEM (OFFRIDX + 128 * 4)

__global__ __launch_bounds__(256) void gemm_mma_kernel(
    const float* __restrict__ node_emb,
    const float* __restrict__ ent_tab,
    const float* __restrict__ rel_tab,
    const float* __restrict__ W_ih,
    const float* __restrict__ W_hh,
    const float* __restrict__ b_ih,
    const float* __restrict__ b_hh,
    const int*   __restrict__ aim_ent,
    float* __restrict__ out_gh,
    float* __restrict__ out_gi_ent,
    float* __restrict__ out_gi_rel)
{
    extern __shared__ char sm[];
    uint32_t* As = reinterpret_cast<uint32_t*>(sm + OFFA);
    uint32_t* Bs = reinterpret_cast<uint32_t*>(sm + OFFB);
    float*    sh_bias = reinterpret_cast<float*>(sm + OFFBIAS);
    int*      sh_ridx = reinterpret_cast<int*>(sm + OFFRIDX);

    const int tid  = threadIdx.x;
    const int wid  = tid >> 5;
    const int lane = tid & 31;

    int bx = blockIdx.x;
    const float* A; const int* gather = nullptr; int nrows;
    const float* W; int ldw, woff; const float* bias; float* out;
    int tile, gate;
    if (bx < 774) {
        tile = bx / 3; gate = bx % 3;
        A = node_emb; nrows = BB * NODES;
        W = W_hh; ldw = 128; woff = 0; bias = b_hh; out = out_gh;
    } else if (bx < 870) {
        int i = bx - 774; tile = i / 3; gate = i % 3;
        A = ent_tab; gather = aim_ent; nrows = BB * TOPK;
        W = W_ih; ldw = 256; woff = 0; bias = b_ih; out = out_gi_ent;
    } else {
        int i = bx - 870; tile = i / 3; gate = i % 3;
        A = rel_tab; nrows = 400;
        W = W_ih; ldw = 256; woff = 128; bias = nullptr; out = out_gi_rel;
    }
    const int row0 = tile * 128;

    if (tid < 128) {
        int r = row0 + tid;
        sh_ridx[tid] = (r < nrows) ? (gather ? gather[r] : r) : -1;
        sh_bias[tid] = bias ? bias[gate * 128 + tid] : 0.0f;
    }
    __syncthreads();

    for (int idx = tid; idx < 128 * 32; idx += 256) {
        int i  = idx >> 5;
        int k4 = (idx & 31) << 2;
        int ridx = sh_ridx[i];
        float4 v = make_float4(0.f, 0.f, 0.f, 0.f);
        if (ridx >= 0)
            v = *reinterpret_cast<const float4*>(&A[(size_t)ridx * 128 + k4]);
        uint32_t* p = &As[i * APITCH + k4];
        p[0] = f2tf32(v.x); p[1] = f2tf32(v.y); p[2] = f2tf32(v.z); p[3] = f2tf32(v.w);
    }
    for (int idx = tid; idx < 128 * 32; idx += 256) {
        int n  = idx >> 5;
        int k4 = (idx & 31) << 2;
        float4 v = *reinterpret_cast<const float4*>(&W[(size_t)(gate * 128 + n) * ldw + woff + k4]);
        uint32_t* p = &Bs[n * APITCH + k4];
        p[0] = f2tf32(v.x); p[1] = f2tf32(v.y); p[2] = f2tf32(v.z); p[3] = f2tf32(v.w);
    }
    __syncthreads();

    const int quad  = lane >> 2;
    const int tq    = lane & 3;
    const int rbase = (wid >> 2) * 64;
    const int cbase = (wid & 3) * 32;

    float acc[4][4][4];
#pragma unroll
    for (int mt = 0; mt < 4; mt++)
#pragma unroll
        for (int nt = 0; nt < 4; nt++)
#pragma unroll
            for (int r = 0; r < 4; r++) acc[mt][nt][r] = 0.f;

#pragma unroll
    for (int ks = 0; ks < 16; ks++) {
        const int k0 = ks * 8;
        uint32_t af[4][4];
#pragma unroll
        for (int mt = 0; mt < 4; mt++) {
            int r = rbase + mt * 16 + quad;
            af[mt][0] = As[r * APITCH + k0 + tq];
            af[mt][1] = As[(r + 8) * APITCH + k0 + tq];
            af[mt][2] = As[r * APITCH + k0 + tq + 4];
            af[mt][3] = As[(r + 8) * APITCH + k0 + tq + 4];
        }
        uint32_t bf[4][2];
#pragma unroll
        for (int nt = 0; nt < 4; nt++) {
            int c = cbase + nt * 8 + quad;
            bf[nt][0] = Bs[c * APITCH + k0 + tq];
            bf[nt][1] = Bs[c * APITCH + k0 + tq + 4];
        }
#pragma unroll
        for (int mt = 0; mt < 4; mt++)
#pragma unroll
            for (int nt = 0; nt < 4; nt++)
                mma_tf32(acc[mt][nt], af[mt], bf[nt]);
    }

#pragma unroll
    for (int mt = 0; mt < 4; mt++) {
#pragma unroll
        for (int nt = 0; nt < 4; nt++) {
            const int col = cbase + nt * 8 + tq * 2;
            const float b0 = sh_bias[col], b1 = sh_bias[col + 1];
            const int row = row0 + rbase + mt * 16 + quad;
            if (row < nrows)
                *reinterpret_cast<float2*>(&out[(size_t)row * G3 + gate * 128 + col]) =
                    make_float2(acc[mt][nt][0] + b0, acc[mt][nt][1] + b1);
            if (row + 8 < nrows)
                *reinterpret_cast<float2*>(&out[(size_t)(row + 8) * G3 + gate * 128 + col]) =
                    make_float2(acc[mt][nt][2] + b0, acc[mt][nt][3] + b1);
        }
    }
}

// ---------------------------------------------------------------------------
// Kernel 3: winner mask (last occurrence of duplicate aim_node wins)
// ---------------------------------------------------------------------------
__global__ void dupmask_kernel(const int* __restrict__ aim_nodes, int* __restrict__ win) {
    const int b = blockIdx.x;
    const int t = threadIdx.x;
    const int node = aim_nodes[b * TOPK + t];
    unsigned grp = __match_any_sync(0xFFFFFFFFu, node);
    int winner = (31 - __clz(grp)) == t;      // highest lane in match group
    win[b * TOPK + t] = winner ? node : -1;
}

// ---------------------------------------------------------------------------
// Kernel 4: GRU aggregation per (batch, 32-channel chunk), fused scatter
// ---------------------------------------------------------------------------
#define OFF_GH   0
#define OFF_H    (258 * 96 * 4)
#define OFF_GI   (OFF_H + 258 * 32 * 4)
#define OFF_NB   (OFF_GI + 32 * 96 * 4)
#define OFF_NUM  (OFF_NB + 32 * 64 * 8)
#define OFF_AIM  (OFF_NUM + 32 * 4)
#define AGG_SMEM (OFF_AIM + 32 * 4)

__global__ __launch_bounds__(512) void aggregate_kernel(
    const float* __restrict__ node_emb,
    const float* __restrict__ gi_rel,
    const float* __restrict__ gi_ent,
    const float* __restrict__ gh_all,
    const int2*  __restrict__ neighbors,
    const int*   __restrict__ nb_num,
    const int*   __restrict__ win,
    float* __restrict__ out)
{
    extern __shared__ char smraw[];
    float* sh_gh  = reinterpret_cast<float*>(smraw + OFF_GH);
    float* sh_h   = reinterpret_cast<float*>(smraw + OFF_H);
    float* sh_gi  = reinterpret_cast<float*>(smraw + OFF_GI);
    int2*  sh_nb  = reinterpret_cast<int2*>(smraw + OFF_NB);
    int*   sh_num = reinterpret_cast<int*>(smraw + OFF_NUM);
    int*   sh_aim = reinterpret_cast<int*>(smraw + OFF_AIM);

    const int tid = threadIdx.x;
    const int c   = blockIdx.x;
    const int b   = blockIdx.y;
    const int cc0 = c * 32;

    for (int idx = tid; idx < 258 * 24; idx += 512) {
        int n = idx / 24, q = idx % 24;
        int gate = q >> 3, jj = (q & 7) * 4;
        float4 v = *reinterpret_cast<const float4*>(
            &gh_all[((size_t)b * NODES + n) * G3 + gate * 128 + cc0 + jj]);
        *reinterpret_cast<float4*>(&sh_gh[(n * 3 + gate) * 32 + jj]) = v;
    }
    for (int idx = tid; idx < 258 * 8; idx += 512) {
        int n = idx >> 3, jj = (idx & 7) * 4;
        float4 v = *reinterpret_cast<const float4*>(
            &node_emb[((size_t)b * NODES + n) * HDIM + cc0 + jj]);
        *reinterpret_cast<float4*>(&sh_h[n * 32 + jj]) = v;
    }
    for (int idx = tid; idx < 32 * 24; idx += 512) {
        int t = idx / 24, q = idx % 24;
        int gate = q >> 3, jj = (q & 7) * 4;
        float4 v = *reinterpret_cast<const float4*>(
            &gi_ent[((size_t)b * TOPK + t) * G3 + gate * 128 + cc0 + jj]);
        *reinterpret_cast<float4*>(&sh_gi[(t * 3 + gate) * 32 + jj]) = v;
    }
    for (int idx = tid; idx < TOPK * MN; idx += 512)
        sh_nb[idx] = neighbors[(size_t)b * TOPK * MN + idx];
    if (tid < TOPK) {
        sh_num[tid] = nb_num[b * TOPK + tid];
        sh_aim[tid] = win[b * TOPK + tid];
    }
    __syncthreads();

    const int warp = tid >> 5;
    const int lane = tid & 31;

    for (int t = warp; t < TOPK; t += 16) {
        const float gir = sh_gi[(t * 3 + 0) * 32 + lane];
        const float giz = sh_gi[(t * 3 + 1) * 32 + lane];
        const float gin = sh_gi[(t * 3 + 2) * 32 + lane];
        const int   num = sh_num[t];
        const int   aim = sh_aim[t];

        float acc = 0.f;
        for (int base = 0; base < num; base += 8) {
            const int cnt = min(8, num - base);
            int   cn[8]; float r0[8], r1[8], r2[8];
#pragma unroll
            for (int j = 0; j < 8; j++) {
                if (j < cnt) {
                    int2 nb = sh_nb[t * MN + base + j];
                    cn[j] = nb.x;
                    const float* gr = gi_rel + (size_t)nb.y * G3 + cc0 + lane;
                    r0[j] = __ldg(gr);
                    r1[j] = __ldg(gr + 128);
                    r2[j] = __ldg(gr + 256);
                }
            }
#pragma unroll
            for (int j = 0; j < 8; j++) {
                if (j < cnt) {
                    const float* gh = sh_gh + cn[j] * 96 + lane;
                    const float  h  = sh_h[cn[j] * 32 + lane];
                    float r = sigmoid_t(gir + r0[j] + gh[0]);
                    float z = sigmoid_t(giz + r1[j] + gh[32]);
                    float n = tanh_ap(fmaf(r, gh[64], gin + r2[j]));
                    acc += fmaf(z, h - n, n);
                }
            }
        }
        if (aim >= 0) {
            float u = (num > 0) ? acc / (float)num : 0.f;
            out[((size_t)b * NODES + aim) * HDIM + cc0 + lane] = u;
        }
    }
}

// ---------------------------------------------------------------------------
// Host launcher
// ---------------------------------------------------------------------------
extern "C" void kernel_launch(void* const* d_in, const int* in_sizes, int n_in,
                              void* d_out, int out_size)
{
    const float* node_emb = (const float*)d_in[0];
    const float* ent_tab  = (const float*)d_in[1];
    const float* rel_tab  = (const float*)d_in[2];
    const float* W_ih     = (const float*)d_in[3];
    const float* W_hh     = (const float*)d_in[4];
    const float* b_ih     = (const float*)d_in[5];
    const float* b_hh     = (const float*)d_in[6];
    const int*   aim_nd   = (const int*)d_in[7];
    const int*   aim_ent  = (const int*)d_in[8];
    const int*   nbrs     = (const int*)d_in[9];
    const int*   nb_num   = (const int*)d_in[10];
    float* out = (float*)d_out;

    float *p_gi_rel, *p_gi_ent, *p_gh; int* p_win;
    cudaGetSymbolAddress((void**)&p_gi_rel, g_gi_rel);
    cudaGetSymbolAddress((void**)&p_gi_ent, g_gi_ent);
    cudaGetSymbolAddress((void**)&p_gh,     g_gh);
    cudaGetSymbolAddress((void**)&p_win,    g_win);

    cudaFuncSetAttribute(gemm_mma_kernel,
        cudaFuncAttributeMaxDynamicSharedMemorySize, GEMM_SMEM);
    cudaFuncSetAttribute(aggregate_kernel,
        cudaFuncAttributeMaxDynamicSharedMemorySize, AGG_SMEM);

    // 1) copy base embeddings to output
    const int n4 = (BB * NODES * HDIM) / 4;
    copy_kernel<<<2048, 256>>>((const float4*)node_emb, (float4*)out, n4);

    // 2) fused GEMMs
    gemm_mma_kernel<<<882, 256, GEMM_SMEM>>>(
        node_emb, ent_tab, rel_tab, W_ih, W_hh, b_ih, b_hh, aim_ent,
        p_gh, p_gi_ent, p_gi_rel);

    // 3) winner mask
    dupmask_kernel<<<BB, 32>>>(aim_nd, p_win);

    // 4) GRU + masked mean aggregation + fused scatter  (profiling slot #4)
    aggregate_kernel<<<dim3(4, BB), 512, AGG_SMEM>>>(
        node_emb, p_gi_rel, p_gi_ent, p_gh,
        (const int2*)nbrs, nb_num, p_win, out);
}

// round 5
// speedup vs baseline: 2.3153x; 1.5031x over previous
#include <cuda_runtime.h>
#include <cstdint>

// Problem constants
#define BB      128
#define TOPK    32
#define MN      64
#define NODES   258        // MAX_NODES + 2
#define HDIM    128
#define G3      384        // 3*H

// ---------------------------------------------------------------------------
// Device scratch
// ---------------------------------------------------------------------------
__device__ float    g_gi_rel[400 * G3];
__device__ float    g_gi_ent[BB * TOPK * G3];
__device__ uint16_t g_gh16 [BB * NODES * G3];   // gh in bf16

// ---------------------------------------------------------------------------
// Helpers
// ---------------------------------------------------------------------------
__device__ __forceinline__ float tanh_ap(float x) {
    float y; asm("tanh.approx.f32 %0, %1;" : "=f"(y) : "f"(x)); return y;
}
__device__ __forceinline__ float sigmoid_t(float x) {
    return fmaf(0.5f, tanh_ap(0.5f * x), 0.5f);
}
__device__ __forceinline__ uint32_t f2tf32(float f) {
    uint32_t u;
    asm("cvt.rna.tf32.f32 %0, %1;" : "=r"(u) : "f"(f));
    return u;
}
__device__ __forceinline__ float bf2f(uint16_t u) {
    return __uint_as_float(((uint32_t)u) << 16);
}
__device__ __forceinline__ uint32_t f2bf2(float lo, float hi) {
    uint32_t r;
    asm("cvt.rn.bf16x2.f32 %0, %1, %2;" : "=r"(r) : "f"(hi), "f"(lo));
    return r;
}
__device__ __forceinline__ void mma_tf32(float* d, const uint32_t* a, const uint32_t* b) {
    asm volatile(
        "mma.sync.aligned.m16n8k8.row.col.f32.tf32.tf32.f32 "
        "{%0,%1,%2,%3}, {%4,%5,%6,%7}, {%8,%9}, {%0,%1,%2,%3};"
        : "+f"(d[0]), "+f"(d[1]), "+f"(d[2]), "+f"(d[3])
        : "r"(a[0]), "r"(a[1]), "r"(a[2]), "r"(a[3]), "r"(b[0]), "r"(b[1]));
}

// ---------------------------------------------------------------------------
// Kernel 1: fused tf32 mma.sync GEMM (882 CTAs, routed by blockIdx.x)
//   [0,774):   gh16   = bf16(node_emb @ W_hh^T + b_hh)
//   [774,870): gi_ent = ent_tab[aim_ent] @ W_ih[:,:128]^T + b_ih   (f32)
//   [870,882): gi_rel = rel_tab @ W_ih[:,128:256]^T                (f32)
// ---------------------------------------------------------------------------
#define APITCH 132
#define OFFA    0
#define OFFB    (128 * APITCH * 4)
#define OFFBIAS (OFFB + 128 * APITCH * 4)
#define OFFRIDX (OFFBIAS + 128 * 4)
#define GEMM_SMEM (OFFRIDX + 128 * 4)

__global__ __launch_bounds__(256) void gemm_mma_kernel(
    const float* __restrict__ node_emb,
    const float* __restrict__ ent_tab,
    const float* __restrict__ rel_tab,
    const float* __restrict__ W_ih,
    const float* __restrict__ W_hh,
    const float* __restrict__ b_ih,
    const float* __restrict__ b_hh,
    const int*   __restrict__ aim_ent,
    uint16_t* __restrict__ out_gh,
    float* __restrict__ out_gi_ent,
    float* __restrict__ out_gi_rel)
{
    extern __shared__ char sm[];
    uint32_t* As = reinterpret_cast<uint32_t*>(sm + OFFA);
    uint32_t* Bs = reinterpret_cast<uint32_t*>(sm + OFFB);
    float*    sh_bias = reinterpret_cast<float*>(sm + OFFBIAS);
    int*      sh_ridx = reinterpret_cast<int*>(sm + OFFRIDX);

    const int tid  = threadIdx.x;
    const int wid  = tid >> 5;
    const int lane = tid & 31;

    int bx = blockIdx.x;
    const float* A; const int* gather = nullptr; int nrows;
    const float* W; int ldw, woff; const float* bias; float* outf = nullptr;
    int tile, gate, obf = 0;
    if (bx < 774) {
        tile = bx / 3; gate = bx % 3;
        A = node_emb; nrows = BB * NODES;
        W = W_hh; ldw = 128; woff = 0; bias = b_hh; obf = 1;
    } else if (bx < 870) {
        int i = bx - 774; tile = i / 3; gate = i % 3;
        A = ent_tab; gather = aim_ent; nrows = BB * TOPK;
        W = W_ih; ldw = 256; woff = 0; bias = b_ih; outf = out_gi_ent;
    } else {
        int i = bx - 870; tile = i / 3; gate = i % 3;
        A = rel_tab; nrows = 400;
        W = W_ih; ldw = 256; woff = 128; bias = nullptr; outf = out_gi_rel;
    }
    const int row0 = tile * 128;

    if (tid < 128) {
        int r = row0 + tid;
        sh_ridx[tid] = (r < nrows) ? (gather ? gather[r] : r) : -1;
        sh_bias[tid] = bias ? bias[gate * 128 + tid] : 0.0f;
    }
    __syncthreads();

    for (int idx = tid; idx < 128 * 32; idx += 256) {
        int i  = idx >> 5;
        int k4 = (idx & 31) << 2;
        int ridx = sh_ridx[i];
        float4 v = make_float4(0.f, 0.f, 0.f, 0.f);
        if (ridx >= 0)
            v = *reinterpret_cast<const float4*>(&A[(size_t)ridx * 128 + k4]);
        uint32_t* p = &As[i * APITCH + k4];
        p[0] = f2tf32(v.x); p[1] = f2tf32(v.y); p[2] = f2tf32(v.z); p[3] = f2tf32(v.w);
    }
    for (int idx = tid; idx < 128 * 32; idx += 256) {
        int n  = idx >> 5;
        int k4 = (idx & 31) << 2;
        float4 v = *reinterpret_cast<const float4*>(&W[(size_t)(gate * 128 + n) * ldw + woff + k4]);
        uint32_t* p = &Bs[n * APITCH + k4];
        p[0] = f2tf32(v.x); p[1] = f2tf32(v.y); p[2] = f2tf32(v.z); p[3] = f2tf32(v.w);
    }
    __syncthreads();

    const int quad  = lane >> 2;
    const int tq    = lane & 3;
    const int rbase = (wid >> 2) * 64;
    const int cbase = (wid & 3) * 32;

    float acc[4][4][4];
#pragma unroll
    for (int mt = 0; mt < 4; mt++)
#pragma unroll
        for (int nt = 0; nt < 4; nt++)
#pragma unroll
            for (int r = 0; r < 4; r++) acc[mt][nt][r] = 0.f;

#pragma unroll
    for (int ks = 0; ks < 16; ks++) {
        const int k0 = ks * 8;
        uint32_t af[4][4];
#pragma unroll
        for (int mt = 0; mt < 4; mt++) {
            int r = rbase + mt * 16 + quad;
            af[mt][0] = As[r * APITCH + k0 + tq];
            af[mt][1] = As[(r + 8) * APITCH + k0 + tq];
            af[mt][2] = As[r * APITCH + k0 + tq + 4];
            af[mt][3] = As[(r + 8) * APITCH + k0 + tq + 4];
        }
        uint32_t bf[4][2];
#pragma unroll
        for (int nt = 0; nt < 4; nt++) {
            int c = cbase + nt * 8 + quad;
            bf[nt][0] = Bs[c * APITCH + k0 + tq];
            bf[nt][1] = Bs[c * APITCH + k0 + tq + 4];
        }
#pragma unroll
        for (int mt = 0; mt < 4; mt++)
#pragma unroll
            for (int nt = 0; nt < 4; nt++)
                mma_tf32(acc[mt][nt], af[mt], bf[nt]);
    }

#pragma unroll
    for (int mt = 0; mt < 4; mt++) {
#pragma unroll
        for (int nt = 0; nt < 4; nt++) {
            const int col = cbase + nt * 8 + tq * 2;
            const float b0 = sh_bias[col], b1 = sh_bias[col + 1];
            const int r1 = row0 + rbase + mt * 16 + quad;
            const int r2 = r1 + 8;
            if (obf) {
                if (r1 < nrows)
                    *reinterpret_cast<uint32_t*>(
                        &out_gh[(size_t)r1 * G3 + gate * 128 + col]) =
                        f2bf2(acc[mt][nt][0] + b0, acc[mt][nt][1] + b1);
                if (r2 < nrows)
                    *reinterpret_cast<uint32_t*>(
                        &out_gh[(size_t)r2 * G3 + gate * 128 + col]) =
                        f2bf2(acc[mt][nt][2] + b0, acc[mt][nt][3] + b1);
            } else {
                if (r1 < nrows)
                    *reinterpret_cast<float2*>(&outf[(size_t)r1 * G3 + gate * 128 + col]) =
                        make_float2(acc[mt][nt][0] + b0, acc[mt][nt][1] + b1);
                if (r2 < nrows)
                    *reinterpret_cast<float2*>(&outf[(size_t)r2 * G3 + gate * 128 + col]) =
                        make_float2(acc[mt][nt][2] + b0, acc[mt][nt][3] + b1);
            }
        }
    }
}

// ---------------------------------------------------------------------------
// Kernel 2: GRU aggregation per (batch, 32-ch chunk); fused base-copy,
// dup-mask, and scatter. 2 CTAs/SM.
// ---------------------------------------------------------------------------
#define OFF_GH   0                               // uint16[258*96]  = 49536 B
#define OFF_H    49536                           // float [258*32]  = 33024 B
#define OFF_GI   (OFF_H + 33024)                 // float [32*96]   = 12288 B
#define OFF_NB   (OFF_GI + 12288)                // int2  [32*64]   = 16384 B
#define OFF_NUM  (OFF_NB + 16384)                // int[32]
#define OFF_AIM  (OFF_NUM + 128)                 // int[32]
#define AGG_SMEM (OFF_AIM + 128)                 // 111616 B

__global__ __launch_bounds__(512, 2) void aggregate_kernel(
    const float*    __restrict__ node_emb,
    const float*    __restrict__ gi_rel,
    const float*    __restrict__ gi_ent,
    const uint16_t* __restrict__ gh_all,
    const int2*     __restrict__ neighbors,
    const int*      __restrict__ nb_num,
    const int*      __restrict__ aim_nodes,
    float* __restrict__ out)
{
    extern __shared__ char smraw[];
    uint16_t* sh_gh  = reinterpret_cast<uint16_t*>(smraw + OFF_GH);
    float*    sh_h   = reinterpret_cast<float*>(smraw + OFF_H);
    float*    sh_gi  = reinterpret_cast<float*>(smraw + OFF_GI);
    int2*     sh_nb  = reinterpret_cast<int2*>(smraw + OFF_NB);
    int*      sh_num = reinterpret_cast<int*>(smraw + OFF_NUM);
    int*      sh_aim = reinterpret_cast<int*>(smraw + OFF_AIM);

    const int tid = threadIdx.x;
    const int c   = blockIdx.x;
    const int b   = blockIdx.y;
    const int cc0 = c * 32;

    // gh slice (bf16): 258 nodes x 3 gates x 32ch -> 3096 x uint4(8 bf16)
    for (int idx = tid; idx < 258 * 12; idx += 512) {
        int n = idx / 12, q = idx % 12;
        int gate = q >> 2, j8 = (q & 3) * 8;
        uint4 v = *reinterpret_cast<const uint4*>(
            &gh_all[((size_t)b * NODES + n) * G3 + gate * 128 + cc0 + j8]);
        *reinterpret_cast<uint4*>(&sh_gh[(n * 3 + gate) * 32 + j8]) = v;
    }
    // h slice (f32) + fused base copy to out
    for (int idx = tid; idx < 258 * 8; idx += 512) {
        int n = idx >> 3, jj = (idx & 7) * 4;
        float4 v = *reinterpret_cast<const float4*>(
            &node_emb[((size_t)b * NODES + n) * HDIM + cc0 + jj]);
        *reinterpret_cast<float4*>(&sh_h[n * 32 + jj]) = v;
        *reinterpret_cast<float4*>(&out[((size_t)b * NODES + n) * HDIM + cc0 + jj]) = v;
    }
    // gi_ent slice (f32)
    for (int idx = tid; idx < 32 * 24; idx += 512) {
        int t = idx / 24, q = idx % 24;
        int gate = q >> 3, jj = (q & 7) * 4;
        float4 v = *reinterpret_cast<const float4*>(
            &gi_ent[((size_t)b * TOPK + t) * G3 + gate * 128 + cc0 + jj]);
        *reinterpret_cast<float4*>(&sh_gi[(t * 3 + gate) * 32 + jj]) = v;
    }
    // neighbor list + counts
    for (int idx = tid; idx < TOPK * MN; idx += 512)
        sh_nb[idx] = neighbors[(size_t)b * TOPK * MN + idx];
    if (tid < TOPK)
        sh_num[tid] = nb_num[b * TOPK + tid];
    // duplicate-winner mask (warp 1, full warp)
    if (tid >= 32 && tid < 64) {
        int t = tid - 32;
        int node = aim_nodes[b * TOPK + t];
        unsigned grp = __match_any_sync(0xFFFFFFFFu, node);
        int winner = (31 - __clz(grp)) == t;
        sh_aim[t] = winner ? node : -1;
    }
    __syncthreads();

    const int warp = tid >> 5;
    const int lane = tid & 31;

    for (int t = warp; t < TOPK; t += 16) {
        const float gir = sh_gi[(t * 3 + 0) * 32 + lane];
        const float giz = sh_gi[(t * 3 + 1) * 32 + lane];
        const float gin = sh_gi[(t * 3 + 2) * 32 + lane];
        const int   num = sh_num[t];
        const int   aim = sh_aim[t];

        float acc = 0.f;
        for (int base = 0; base < num; base += 8) {
            const int cnt = min(8, num - base);
            int   cn[8]; float r0[8], r1[8], r2[8];
#pragma unroll
            for (int j = 0; j < 8; j++) {
                if (j < cnt) {
                    int2 nb = sh_nb[t * MN + base + j];
                    cn[j] = nb.x;
                    const float* gr = gi_rel + (size_t)nb.y * G3 + cc0 + lane;
                    r0[j] = __ldg(gr);
                    r1[j] = __ldg(gr + 128);
                    r2[j] = __ldg(gr + 256);
                }
            }
#pragma unroll
            for (int j = 0; j < 8; j++) {
                if (j < cnt) {
                    const uint16_t* gh = sh_gh + cn[j] * 96 + lane;
                    const float h  = sh_h[cn[j] * 32 + lane];
                    float r = sigmoid_t(gir + r0[j] + bf2f(gh[0]));
                    float z = sigmoid_t(giz + r1[j] + bf2f(gh[32]));
                    float n = tanh_ap(fmaf(r, bf2f(gh[64]), gin + r2[j]));
                    acc += fmaf(z, h - n, n);
                }
            }
        }
        if (aim >= 0) {
            float u = (num > 0) ? acc / (float)num : 0.f;
            out[((size_t)b * NODES + aim) * HDIM + cc0 + lane] = u;
        }
    }
}

// ---------------------------------------------------------------------------
// Host launcher
// ---------------------------------------------------------------------------
extern "C" void kernel_launch(void* const* d_in, const int* in_sizes, int n_in,
                              void* d_out, int out_size)
{
    const float* node_emb = (const float*)d_in[0];
    const float* ent_tab  = (const float*)d_in[1];
    const float* rel_tab  = (const float*)d_in[2];
    const float* W_ih     = (const float*)d_in[3];
    const float* W_hh     = (const float*)d_in[4];
    const float* b_ih     = (const float*)d_in[5];
    const float* b_hh     = (const float*)d_in[6];
    const int*   aim_nd   = (const int*)d_in[7];
    const int*   aim_ent  = (const int*)d_in[8];
    const int*   nbrs     = (const int*)d_in[9];
    const int*   nb_num   = (const int*)d_in[10];
    float* out = (float*)d_out;

    float *p_gi_rel, *p_gi_ent; uint16_t* p_gh;
    cudaGetSymbolAddress((void**)&p_gi_rel, g_gi_rel);
    cudaGetSymbolAddress((void**)&p_gi_ent, g_gi_ent);
    cudaGetSymbolAddress((void**)&p_gh,     g_gh16);

    cudaFuncSetAttribute(gemm_mma_kernel,
        cudaFuncAttributeMaxDynamicSharedMemorySize, GEMM_SMEM);
    cudaFuncSetAttribute(aggregate_kernel,
        cudaFuncAttributeMaxDynamicSharedMemorySize, AGG_SMEM);

    // 1) fused GEMMs
    gemm_mma_kernel<<<882, 256, GEMM_SMEM>>>(
        node_emb, ent_tab, rel_tab, W_ih, W_hh, b_ih, b_hh, aim_ent,
        p_gh, p_gi_ent, p_gi_rel);

    // 2) GRU + masked mean + fused base-copy/dupmask/scatter
    aggregate_kernel<<<dim3(4, BB), 512, AGG_SMEM>>>(
        node_emb, p_gi_rel, p_gi_ent, p_gh,
        (const int2*)nbrs, nb_num, aim_nd, out);
}

// round 6
// speedup vs baseline: 3.1264x; 1.3503x over previous
#include <cuda_runtime.h>
#include <cstdint>

// Problem constants
#define BB      128
#define TOPK    32
#define MN      64
#define NODES   258        // MAX_NODES + 2
#define HDIM    128
#define G3      384        // 3*H

// ---------------------------------------------------------------------------
// Device scratch
// ---------------------------------------------------------------------------
__device__ float    g_gi_rel[400 * G3];
__device__ float    g_gi_ent[BB * TOPK * G3];
__device__ uint16_t g_gh16 [BB * NODES * G3];   // gh in bf16

// ---------------------------------------------------------------------------
// Helpers
// ---------------------------------------------------------------------------
__device__ __forceinline__ float tanh_ap(float x) {
    float y; asm("tanh.approx.f32 %0, %1;" : "=f"(y) : "f"(x)); return y;
}
__device__ __forceinline__ float sigmoid_t(float x) {
    return fmaf(0.5f, tanh_ap(0.5f * x), 0.5f);
}
__device__ __forceinline__ float bf2f(uint16_t u) {
    return __uint_as_float(((uint32_t)u) << 16);
}
__device__ __forceinline__ uint32_t f2bf2(float lo, float hi) {
    uint32_t r;
    asm("cvt.rn.bf16x2.f32 %0, %1, %2;" : "=r"(r) : "f"(hi), "f"(lo));
    return r;
}
__device__ __forceinline__ void mma_bf16(float* d, const uint32_t* a, const uint32_t* b) {
    asm volatile(
        "mma.sync.aligned.m16n8k16.row.col.f32.bf16.bf16.f32 "
        "{%0,%1,%2,%3}, {%4,%5,%6,%7}, {%8,%9}, {%0,%1,%2,%3};"
        : "+f"(d[0]), "+f"(d[1]), "+f"(d[2]), "+f"(d[3])
        : "r"(a[0]), "r"(a[1]), "r"(a[2]), "r"(a[3]), "r"(b[0]), "r"(b[1]));
}

// ---------------------------------------------------------------------------
// Kernel 1: fused bf16 mma.sync GEMM (882 CTAs, routed by blockIdx.x)
//   [0,774):   gh16   = bf16(node_emb @ W_hh^T + b_hh)
//   [774,870): gi_ent = ent_tab[aim_ent] @ W_ih[:,:128]^T + b_ih   (f32)
//   [870,882): gi_rel = rel_tab @ W_ih[:,128:256]^T                (f32)
// Tiles in bf16 (u32 = 2 bf16 along k), pitch 68 u32 -> conflict-free frags.
// ---------------------------------------------------------------------------
#define APITCH 68                                // u32 units per row
#define OFFA    0
#define OFFB    (128 * APITCH * 4)               // 34816
#define OFFBIAS (OFFB + 128 * APITCH * 4)        // 69632
#define OFFRIDX (OFFBIAS + 128 * 4)              // 70144
#define GEMM_SMEM (OFFRIDX + 128 * 4)            // 70656

__global__ __launch_bounds__(256, 2) void gemm_mma_kernel(
    const float* __restrict__ node_emb,
    const float* __restrict__ ent_tab,
    const float* __restrict__ rel_tab,
    const float* __restrict__ W_ih,
    const float* __restrict__ W_hh,
    const float* __restrict__ b_ih,
    const float* __restrict__ b_hh,
    const int*   __restrict__ aim_ent,
    uint16_t* __restrict__ out_gh,
    float* __restrict__ out_gi_ent,
    float* __restrict__ out_gi_rel)
{
    extern __shared__ char sm[];
    uint32_t* As = reinterpret_cast<uint32_t*>(sm + OFFA);   // [row][k/2] pitch 68
    uint32_t* Bs = reinterpret_cast<uint32_t*>(sm + OFFB);   // [n][k/2]   pitch 68
    float*    sh_bias = reinterpret_cast<float*>(sm + OFFBIAS);
    int*      sh_ridx = reinterpret_cast<int*>(sm + OFFRIDX);

    const int tid  = threadIdx.x;
    const int wid  = tid >> 5;
    const int lane = tid & 31;

    int bx = blockIdx.x;
    const float* A; const int* gather = nullptr; int nrows;
    const float* W; int ldw, woff; const float* bias; float* outf = nullptr;
    int tile, gate, obf = 0;
    if (bx < 774) {
        tile = bx / 3; gate = bx % 3;
        A = node_emb; nrows = BB * NODES;
        W = W_hh; ldw = 128; woff = 0; bias = b_hh; obf = 1;
    } else if (bx < 870) {
        int i = bx - 774; tile = i / 3; gate = i % 3;
        A = ent_tab; gather = aim_ent; nrows = BB * TOPK;
        W = W_ih; ldw = 256; woff = 0; bias = b_ih; outf = out_gi_ent;
    } else {
        int i = bx - 870; tile = i / 3; gate = i % 3;
        A = rel_tab; nrows = 400;
        W = W_ih; ldw = 256; woff = 128; bias = nullptr; outf = out_gi_rel;
    }
    const int row0 = tile * 128;

    if (tid < 128) {
        int r = row0 + tid;
        sh_ridx[tid] = (r < nrows) ? (gather ? gather[r] : r) : -1;
        sh_bias[tid] = bias ? bias[gate * 128 + tid] : 0.0f;
    }
    __syncthreads();

    // A tile -> bf16 pairs
    for (int idx = tid; idx < 128 * 32; idx += 256) {
        int i  = idx >> 5;
        int k4 = (idx & 31) << 2;
        int ridx = sh_ridx[i];
        float4 v = make_float4(0.f, 0.f, 0.f, 0.f);
        if (ridx >= 0)
            v = *reinterpret_cast<const float4*>(&A[(size_t)ridx * 128 + k4]);
        uint2 w = make_uint2(f2bf2(v.x, v.y), f2bf2(v.z, v.w));
        *reinterpret_cast<uint2*>(&As[i * APITCH + (k4 >> 1)]) = w;
    }
    // B tile -> bf16 pairs
    for (int idx = tid; idx < 128 * 32; idx += 256) {
        int n  = idx >> 5;
        int k4 = (idx & 31) << 2;
        float4 v = *reinterpret_cast<const float4*>(&W[(size_t)(gate * 128 + n) * ldw + woff + k4]);
        uint2 w = make_uint2(f2bf2(v.x, v.y), f2bf2(v.z, v.w));
        *reinterpret_cast<uint2*>(&Bs[n * APITCH + (k4 >> 1)]) = w;
    }
    __syncthreads();

    const int quad  = lane >> 2;        // 0..7
    const int tq    = lane & 3;         // 0..3
    const int rbase = (wid >> 2) * 64;  // 0 or 64
    const int cbase = (wid & 3) * 32;   // 0,32,64,96

    float acc[4][4][4];
#pragma unroll
    for (int mt = 0; mt < 4; mt++)
#pragma unroll
        for (int nt = 0; nt < 4; nt++)
#pragma unroll
            for (int r = 0; r < 4; r++) acc[mt][nt][r] = 0.f;

#pragma unroll
    for (int ks = 0; ks < 8; ks++) {
        const int k0 = ks * 8;                       // u32 units (16 bf16)
        uint32_t af[4][4];
#pragma unroll
        for (int mt = 0; mt < 4; mt++) {
            int r = rbase + mt * 16 + quad;
            af[mt][0] = As[r * APITCH + k0 + tq];
            af[mt][1] = As[(r + 8) * APITCH + k0 + tq];
            af[mt][2] = As[r * APITCH + k0 + tq + 4];
            af[mt][3] = As[(r + 8) * APITCH + k0 + tq + 4];
        }
        uint32_t bf[4][2];
#pragma unroll
        for (int nt = 0; nt < 4; nt++) {
            int c = cbase + nt * 8 + quad;
            bf[nt][0] = Bs[c * APITCH + k0 + tq];
            bf[nt][1] = Bs[c * APITCH + k0 + tq + 4];
        }
#pragma unroll
        for (int mt = 0; mt < 4; mt++)
#pragma unroll
            for (int nt = 0; nt < 4; nt++)
                mma_bf16(acc[mt][nt], af[mt], bf[nt]);
    }

#pragma unroll
    for (int mt = 0; mt < 4; mt++) {
#pragma unroll
        for (int nt = 0; nt < 4; nt++) {
            const int col = cbase + nt * 8 + tq * 2;
            const float b0 = sh_bias[col], b1 = sh_bias[col + 1];
            const int r1 = row0 + rbase + mt * 16 + quad;
            const int r2 = r1 + 8;
            if (obf) {
                if (r1 < nrows)
                    *reinterpret_cast<uint32_t*>(
                        &out_gh[(size_t)r1 * G3 + gate * 128 + col]) =
                        f2bf2(acc[mt][nt][0] + b0, acc[mt][nt][1] + b1);
                if (r2 < nrows)
                    *reinterpret_cast<uint32_t*>(
                        &out_gh[(size_t)r2 * G3 + gate * 128 + col]) =
                        f2bf2(acc[mt][nt][2] + b0, acc[mt][nt][3] + b1);
            } else {
                if (r1 < nrows)
                    *reinterpret_cast<float2*>(&outf[(size_t)r1 * G3 + gate * 128 + col]) =
                        make_float2(acc[mt][nt][0] + b0, acc[mt][nt][1] + b1);
                if (r2 < nrows)
                    *reinterpret_cast<float2*>(&outf[(size_t)r2 * G3 + gate * 128 + col]) =
                        make_float2(acc[mt][nt][2] + b0, acc[mt][nt][3] + b1);
            }
        }
    }
}

// ---------------------------------------------------------------------------
// Kernel 2: GRU aggregation per (batch, 32-ch chunk); fused base-copy,
// dup-mask, and scatter. 2 CTAs/SM.
// ---------------------------------------------------------------------------
#define OFF_GH   0                               // uint16[258*96]  = 49536 B
#define OFF_H    49536                           // float [258*32]  = 33024 B
#define OFF_GI   (OFF_H + 33024)                 // float [32*96]   = 12288 B
#define OFF_NB   (OFF_GI + 12288)                // int2  [32*64]   = 16384 B
#define OFF_NUM  (OFF_NB + 16384)                // int[32]
#define OFF_AIM  (OFF_NUM + 128)                 // int[32]
#define AGG_SMEM (OFF_AIM + 128)                 // 111616 B

__global__ __launch_bounds__(512, 2) void aggregate_kernel(
    const float*    __restrict__ node_emb,
    const float*    __restrict__ gi_rel,
    const float*    __restrict__ gi_ent,
    const uint16_t* __restrict__ gh_all,
    const int2*     __restrict__ neighbors,
    const int*      __restrict__ nb_num,
    const int*      __restrict__ aim_nodes,
    float* __restrict__ out)
{
    extern __shared__ char smraw[];
    uint16_t* sh_gh  = reinterpret_cast<uint16_t*>(smraw + OFF_GH);
    float*    sh_h   = reinterpret_cast<float*>(smraw + OFF_H);
    float*    sh_gi  = reinterpret_cast<float*>(smraw + OFF_GI);
    int2*     sh_nb  = reinterpret_cast<int2*>(smraw + OFF_NB);
    int*      sh_num = reinterpret_cast<int*>(smraw + OFF_NUM);
    int*      sh_aim = reinterpret_cast<int*>(smraw + OFF_AIM);

    const int tid = threadIdx.x;
    const int c   = blockIdx.x;
    const int b   = blockIdx.y;
    const int cc0 = c * 32;

    for (int idx = tid; idx < 258 * 12; idx += 512) {
        int n = idx / 12, q = idx % 12;
        int gate = q >> 2, j8 = (q & 3) * 8;
        uint4 v = *reinterpret_cast<const uint4*>(
            &gh_all[((size_t)b * NODES + n) * G3 + gate * 128 + cc0 + j8]);
        *reinterpret_cast<uint4*>(&sh_gh[(n * 3 + gate) * 32 + j8]) = v;
    }
    for (int idx = tid; idx < 258 * 8; idx += 512) {
        int n = idx >> 3, jj = (idx & 7) * 4;
        float4 v = *reinterpret_cast<const float4*>(
            &node_emb[((size_t)b * NODES + n) * HDIM + cc0 + jj]);
        *reinterpret_cast<float4*>(&sh_h[n * 32 + jj]) = v;
        *reinterpret_cast<float4*>(&out[((size_t)b * NODES + n) * HDIM + cc0 + jj]) = v;
    }
    for (int idx = tid; idx < 32 * 24; idx += 512) {
        int t = idx / 24, q = idx % 24;
        int gate = q >> 3, jj = (q & 7) * 4;
        float4 v = *reinterpret_cast<const float4*>(
            &gi_ent[((size_t)b * TOPK + t) * G3 + gate * 128 + cc0 + jj]);
        *reinterpret_cast<float4*>(&sh_gi[(t * 3 + gate) * 32 + jj]) = v;
    }
    for (int idx = tid; idx < TOPK * MN; idx += 512)
        sh_nb[idx] = neighbors[(size_t)b * TOPK * MN + idx];
    if (tid < TOPK)
        sh_num[tid] = nb_num[b * TOPK + tid];
    if (tid >= 32 && tid < 64) {
        int t = tid - 32;
        int node = aim_nodes[b * TOPK + t];
        unsigned grp = __match_any_sync(0xFFFFFFFFu, node);
        int winner = (31 - __clz(grp)) == t;
        sh_aim[t] = winner ? node : -1;
    }
    __syncthreads();

    const int warp = tid >> 5;
    const int lane = tid & 31;

    for (int t = warp; t < TOPK; t += 16) {
        const float gir = sh_gi[(t * 3 + 0) * 32 + lane];
        const float giz = sh_gi[(t * 3 + 1) * 32 + lane];
        const float gin = sh_gi[(t * 3 + 2) * 32 + lane];
        const int   num = sh_num[t];
        const int   aim = sh_aim[t];

        float acc = 0.f;
        for (int base = 0; base < num; base += 8) {
            const int cnt = min(8, num - base);
            int   cn[8]; float r0[8], r1[8], r2[8];
#pragma unroll
            for (int j = 0; j < 8; j++) {
                if (j < cnt) {
                    int2 nb = sh_nb[t * MN + base + j];
                    cn[j] = nb.x;
                    const float* gr = gi_rel + (size_t)nb.y * G3 + cc0 + lane;
                    r0[j] = __ldg(gr);
                    r1[j] = __ldg(gr + 128);
                    r2[j] = __ldg(gr + 256);
                }
            }
#pragma unroll
            for (int j = 0; j < 8; j++) {
                if (j < cnt) {
                    const uint16_t* gh = sh_gh + cn[j] * 96 + lane;
                    const float h  = sh_h[cn[j] * 32 + lane];
                    float r = sigmoid_t(gir + r0[j] + bf2f(gh[0]));
                    float z = sigmoid_t(giz + r1[j] + bf2f(gh[32]));
                    float n = tanh_ap(fmaf(r, bf2f(gh[64]), gin + r2[j]));
                    acc += fmaf(z, h - n, n);
                }
            }
        }
        if (aim >= 0) {
            float u = (num > 0) ? acc / (float)num : 0.f;
            out[((size_t)b * NODES + aim) * HDIM + cc0 + lane] = u;
        }
    }
}

// ---------------------------------------------------------------------------
// Host launcher
// ---------------------------------------------------------------------------
extern "C" void kernel_launch(void* const* d_in, const int* in_sizes, int n_in,
                              void* d_out, int out_size)
{
    const float* node_emb = (const float*)d_in[0];
    const float* ent_tab  = (const float*)d_in[1];
    const float* rel_tab  = (const float*)d_in[2];
    const float* W_ih     = (const float*)d_in[3];
    const float* W_hh     = (const float*)d_in[4];
    const float* b_ih     = (const float*)d_in[5];
    const float* b_hh     = (const float*)d_in[6];
    const int*   aim_nd   = (const int*)d_in[7];
    const int*   aim_ent  = (const int*)d_in[8];
    const int*   nbrs     = (const int*)d_in[9];
    const int*   nb_num   = (const int*)d_in[10];
    float* out = (float*)d_out;

    float *p_gi_rel, *p_gi_ent; uint16_t* p_gh;
    cudaGetSymbolAddress((void**)&p_gi_rel, g_gi_rel);
    cudaGetSymbolAddress((void**)&p_gi_ent, g_gi_ent);
    cudaGetSymbolAddress((void**)&p_gh,     g_gh16);

    cudaFuncSetAttribute(gemm_mma_kernel,
        cudaFuncAttributeMaxDynamicSharedMemorySize, GEMM_SMEM);
    cudaFuncSetAttribute(aggregate_kernel,
        cudaFuncAttributeMaxDynamicSharedMemorySize, AGG_SMEM);

    // 1) fused GEMMs (bf16 tensor cores)
    gemm_mma_kernel<<<882, 256, GEMM_SMEM>>>(
        node_emb, ent_tab, rel_tab, W_ih, W_hh, b_ih, b_hh, aim_ent,
        p_gh, p_gi_ent, p_gi_rel);

    // 2) GRU + masked mean + fused base-copy/dupmask/scatter
    aggregate_kernel<<<dim3(4, BB), 512, AGG_SMEM>>>(
        node_emb, p_gi_rel, p_gi_ent, p_gh,
        (const int2*)nbrs, nb_num, aim_nd, out);
}

// round 7
// speedup vs baseline: 3.1286x; 1.0007x over previous
#include <cuda_runtime.h>
#include <cstdint>

// Problem constants
#define BB      128
#define TOPK    32
#define MN      64
#define NODES   258        // MAX_NODES + 2
#define HDIM    128
#define G3      384        // 3*H

// ---------------------------------------------------------------------------
// Device scratch
// ---------------------------------------------------------------------------
__device__ float    g_gi_rel[400 * G3];
__device__ float    g_gi_ent[BB * TOPK * G3];
__device__ uint16_t g_gh16 [BB * NODES * G3];   // gh in bf16

// ---------------------------------------------------------------------------
// Helpers
// ---------------------------------------------------------------------------
__device__ __forceinline__ float tanh_ap(float x) {
    float y; asm("tanh.approx.f32 %0, %1;" : "=f"(y) : "f"(x)); return y;
}
__device__ __forceinline__ float sigmoid_t(float x) {
    return fmaf(0.5f, tanh_ap(0.5f * x), 0.5f);
}
__device__ __forceinline__ float bf2f(uint16_t u) {
    return __uint_as_float(((uint32_t)u) << 16);
}
__device__ __forceinline__ uint32_t f2bf2(float lo, float hi) {
    uint32_t r;
    asm("cvt.rn.bf16x2.f32 %0, %1, %2;" : "=r"(r) : "f"(hi), "f"(lo));
    return r;
}
__device__ __forceinline__ void mma_bf16(float* d, const uint32_t* a, const uint32_t* b) {
    asm volatile(
        "mma.sync.aligned.m16n8k16.row.col.f32.bf16.bf16.f32 "
        "{%0,%1,%2,%3}, {%4,%5,%6,%7}, {%8,%9}, {%0,%1,%2,%3};"
        : "+f"(d[0]), "+f"(d[1]), "+f"(d[2]), "+f"(d[3])
        : "r"(a[0]), "r"(a[1]), "r"(a[2]), "r"(a[3]), "r"(b[0]), "r"(b[1]));
}

// ---------------------------------------------------------------------------
// Kernel 1: fused bf16 mma.sync GEMM (882 CTAs, routed by blockIdx.x)
// ---------------------------------------------------------------------------
#define APITCH 68                                // u32 units per row
#define OFFA    0
#define OFFB    (128 * APITCH * 4)
#define OFFBIAS (OFFB + 128 * APITCH * 4)
#define OFFRIDX (OFFBIAS + 128 * 4)
#define GEMM_SMEM (OFFRIDX + 128 * 4)

__global__ __launch_bounds__(256, 2) void gemm_mma_kernel(
    const float* __restrict__ node_emb,
    const float* __restrict__ ent_tab,
    const float* __restrict__ rel_tab,
    const float* __restrict__ W_ih,
    const float* __restrict__ W_hh,
    const float* __restrict__ b_ih,
    const float* __restrict__ b_hh,
    const int*   __restrict__ aim_ent,
    uint16_t* __restrict__ out_gh,
    float* __restrict__ out_gi_ent,
    float* __restrict__ out_gi_rel)
{
    extern __shared__ char sm[];
    uint32_t* As = reinterpret_cast<uint32_t*>(sm + OFFA);
    uint32_t* Bs = reinterpret_cast<uint32_t*>(sm + OFFB);
    float*    sh_bias = reinterpret_cast<float*>(sm + OFFBIAS);
    int*      sh_ridx = reinterpret_cast<int*>(sm + OFFRIDX);

    const int tid  = threadIdx.x;
    const int wid  = tid >> 5;
    const int lane = tid & 31;

    int bx = blockIdx.x;
    const float* A; const int* gather = nullptr; int nrows;
    const float* W; int ldw, woff; const float* bias; float* outf = nullptr;
    int tile, gate, obf = 0;
    if (bx < 774) {
        tile = bx / 3; gate = bx % 3;
        A = node_emb; nrows = BB * NODES;
        W = W_hh; ldw = 128; woff = 0; bias = b_hh; obf = 1;
    } else if (bx < 870) {
        int i = bx - 774; tile = i / 3; gate = i % 3;
        A = ent_tab; gather = aim_ent; nrows = BB * TOPK;
        W = W_ih; ldw = 256; woff = 0; bias = b_ih; outf = out_gi_ent;
    } else {
        int i = bx - 870; tile = i / 3; gate = i % 3;
        A = rel_tab; nrows = 400;
        W = W_ih; ldw = 256; woff = 128; bias = nullptr; outf = out_gi_rel;
    }
    const int row0 = tile * 128;

    if (tid < 128) {
        int r = row0 + tid;
        sh_ridx[tid] = (r < nrows) ? (gather ? gather[r] : r) : -1;
        sh_bias[tid] = bias ? bias[gate * 128 + tid] : 0.0f;
    }
    __syncthreads();

    for (int idx = tid; idx < 128 * 32; idx += 256) {
        int i  = idx >> 5;
        int k4 = (idx & 31) << 2;
        int ridx = sh_ridx[i];
        float4 v = make_float4(0.f, 0.f, 0.f, 0.f);
        if (ridx >= 0)
            v = *reinterpret_cast<const float4*>(&A[(size_t)ridx * 128 + k4]);
        uint2 w = make_uint2(f2bf2(v.x, v.y), f2bf2(v.z, v.w));
        *reinterpret_cast<uint2*>(&As[i * APITCH + (k4 >> 1)]) = w;
    }
    for (int idx = tid; idx < 128 * 32; idx += 256) {
        int n  = idx >> 5;
        int k4 = (idx & 31) << 2;
        float4 v = *reinterpret_cast<const float4*>(&W[(size_t)(gate * 128 + n) * ldw + woff + k4]);
        uint2 w = make_uint2(f2bf2(v.x, v.y), f2bf2(v.z, v.w));
        *reinterpret_cast<uint2*>(&Bs[n * APITCH + (k4 >> 1)]) = w;
    }
    __syncthreads();

    const int quad  = lane >> 2;
    const int tq    = lane & 3;
    const int rbase = (wid >> 2) * 64;
    const int cbase = (wid & 3) * 32;

    float acc[4][4][4];
#pragma unroll
    for (int mt = 0; mt < 4; mt++)
#pragma unroll
        for (int nt = 0; nt < 4; nt++)
#pragma unroll
            for (int r = 0; r < 4; r++) acc[mt][nt][r] = 0.f;

#pragma unroll
    for (int ks = 0; ks < 8; ks++) {
        const int k0 = ks * 8;
        uint32_t af[4][4];
#pragma unroll
        for (int mt = 0; mt < 4; mt++) {
            int r = rbase + mt * 16 + quad;
            af[mt][0] = As[r * APITCH + k0 + tq];
            af[mt][1] = As[(r + 8) * APITCH + k0 + tq];
            af[mt][2] = As[r * APITCH + k0 + tq + 4];
            af[mt][3] = As[(r + 8) * APITCH + k0 + tq + 4];
        }
        uint32_t bf[4][2];
#pragma unroll
        for (int nt = 0; nt < 4; nt++) {
            int c = cbase + nt * 8 + quad;
            bf[nt][0] = Bs[c * APITCH + k0 + tq];
            bf[nt][1] = Bs[c * APITCH + k0 + tq + 4];
        }
#pragma unroll
        for (int mt = 0; mt < 4; mt++)
#pragma unroll
            for (int nt = 0; nt < 4; nt++)
                mma_bf16(acc[mt][nt], af[mt], bf[nt]);
    }

#pragma unroll
    for (int mt = 0; mt < 4; mt++) {
#pragma unroll
        for (int nt = 0; nt < 4; nt++) {
            const int col = cbase + nt * 8 + tq * 2;
            const float b0 = sh_bias[col], b1 = sh_bias[col + 1];
            const int r1 = row0 + rbase + mt * 16 + quad;
            const int r2 = r1 + 8;
            if (obf) {
                if (r1 < nrows)
                    *reinterpret_cast<uint32_t*>(
                        &out_gh[(size_t)r1 * G3 + gate * 128 + col]) =
                        f2bf2(acc[mt][nt][0] + b0, acc[mt][nt][1] + b1);
                if (r2 < nrows)
                    *reinterpret_cast<uint32_t*>(
                        &out_gh[(size_t)r2 * G3 + gate * 128 + col]) =
                        f2bf2(acc[mt][nt][2] + b0, acc[mt][nt][3] + b1);
            } else {
                if (r1 < nrows)
                    *reinterpret_cast<float2*>(&outf[(size_t)r1 * G3 + gate * 128 + col]) =
                        make_float2(acc[mt][nt][0] + b0, acc[mt][nt][1] + b1);
                if (r2 < nrows)
                    *reinterpret_cast<float2*>(&outf[(size_t)r2 * G3 + gate * 128 + col]) =
                        make_float2(acc[mt][nt][2] + b0, acc[mt][nt][3] + b1);
            }
        }
    }
}

// ---------------------------------------------------------------------------
// Kernel 2: GRU aggregation, load-balanced via compacted worklist.
// Per (batch, 32-ch chunk). 2 CTAs/SM.
// ---------------------------------------------------------------------------
#define OFF_GH   0                               // u16 [258*96]   = 49536
#define OFF_H    49536                           // f32 [258*32]   = 33024
#define OFF_GI   (OFF_H + 33024)                 // f32 [32*96]    = 12288
#define OFF_WORK (OFF_GI + 12288)                // i32 [2048]     =  8192
#define OFF_ACC  (OFF_WORK + 8192)               // f32 [32*32]    =  4096
#define OFF_PREF (OFF_ACC + 4096)                // i32 [33] (pad 144)
#define OFF_NUM  (OFF_PREF + 144)                // i32 [32]
#define OFF_AIM  (OFF_NUM + 128)                 // i32 [32]
#define AGG_SMEM (OFF_AIM + 128)                 // 107,536 B

__global__ __launch_bounds__(512, 2) void aggregate_kernel(
    const float*    __restrict__ node_emb,
    const float*    __restrict__ gi_rel,
    const float*    __restrict__ gi_ent,
    const uint16_t* __restrict__ gh_all,
    const int2*     __restrict__ neighbors,
    const int*      __restrict__ nb_num,
    const int*      __restrict__ aim_nodes,
    float* __restrict__ out)
{
    extern __shared__ char smraw[];
    uint16_t* sh_gh   = reinterpret_cast<uint16_t*>(smraw + OFF_GH);
    float*    sh_h    = reinterpret_cast<float*>(smraw + OFF_H);
    float*    sh_gi   = reinterpret_cast<float*>(smraw + OFF_GI);
    int*      sh_work = reinterpret_cast<int*>(smraw + OFF_WORK);
    float*    sh_acc  = reinterpret_cast<float*>(smraw + OFF_ACC);
    int*      sh_pref = reinterpret_cast<int*>(smraw + OFF_PREF);
    int*      sh_num  = reinterpret_cast<int*>(smraw + OFF_NUM);
    int*      sh_aim  = reinterpret_cast<int*>(smraw + OFF_AIM);

    const int tid = threadIdx.x;
    const int c   = blockIdx.x;
    const int b   = blockIdx.y;
    const int cc0 = c * 32;

    // ---- fill phase ----
    for (int idx = tid; idx < 258 * 12; idx += 512) {
        int n = idx / 12, q = idx % 12;
        int gate = q >> 2, j8 = (q & 3) * 8;
        uint4 v = *reinterpret_cast<const uint4*>(
            &gh_all[((size_t)b * NODES + n) * G3 + gate * 128 + cc0 + j8]);
        *reinterpret_cast<uint4*>(&sh_gh[(n * 3 + gate) * 32 + j8]) = v;
    }
    for (int idx = tid; idx < 258 * 8; idx += 512) {
        int n = idx >> 3, jj = (idx & 7) * 4;
        float4 v = *reinterpret_cast<const float4*>(
            &node_emb[((size_t)b * NODES + n) * HDIM + cc0 + jj]);
        *reinterpret_cast<float4*>(&sh_h[n * 32 + jj]) = v;
        *reinterpret_cast<float4*>(&out[((size_t)b * NODES + n) * HDIM + cc0 + jj]) = v;
    }
    for (int idx = tid; idx < 32 * 24; idx += 512) {
        int t = idx / 24, q = idx % 24;
        int gate = q >> 3, jj = (q & 7) * 4;
        float4 v = *reinterpret_cast<const float4*>(
            &gi_ent[((size_t)b * TOPK + t) * G3 + gate * 128 + cc0 + jj]);
        *reinterpret_cast<float4*>(&sh_gi[(t * 3 + gate) * 32 + jj]) = v;
    }
    if (tid < 1024) {
        int i = tid;
        if (i < 32) sh_num[i] = nb_num[b * TOPK + i];
        sh_acc[tid & 1023] = 0.0f;
    }
    for (int idx = tid; idx < 1024; idx += 512)
        sh_acc[idx] = 0.0f;
    if (tid >= 32 && tid < 64) {
        int t = tid - 32;
        int node = aim_nodes[b * TOPK + t];
        unsigned grp = __match_any_sync(0xFFFFFFFFu, node);
        int winner = (31 - __clz(grp)) == t;
        sh_aim[t] = winner ? node : -1;
    }
    __syncthreads();

    // ---- prefix scan over num (warp 0) ----
    if (tid < 32) {
        int s = sh_num[tid];
#pragma unroll
        for (int o = 1; o < 32; o <<= 1) {
            int x = __shfl_up_sync(0xFFFFFFFFu, s, o);
            if (tid >= o) s += x;
        }
        sh_pref[tid + 1] = s;
        if (tid == 0) sh_pref[0] = 0;
    }
    __syncthreads();

    const int V = sh_pref[32];

    // ---- worklist build: packed (t | node<<5 | rel<<15) ----
    for (int idx = tid; idx < TOPK * MN; idx += 512) {
        int t = idx >> 6, m = idx & 63;
        if (m < sh_num[t]) {
            int2 nb = neighbors[(size_t)b * TOPK * MN + idx];
            sh_work[sh_pref[t] + m] = t | (nb.x << 5) | (nb.y << 15);
        }
    }
    __syncthreads();

    // ---- balanced compute: warp w handles v in [V*w/16, V*(w+1)/16) ----
    const int warp = tid >> 5;
    const int lane = tid & 31;
    const int vbeg = (V * warp) >> 4;
    const int vend = (V * (warp + 1)) >> 4;

    int   cur_t = -1;
    float gir = 0.f, giz = 0.f, gin = 0.f, acc = 0.f;

    for (int v0 = vbeg; v0 < vend; v0 += 8) {
        const int cnt = min(8, vend - v0);
        int tt[8], nd[8]; float r0[8], r1[8], r2[8];
#pragma unroll
        for (int j = 0; j < 8; j++) {
            if (j < cnt) {
                int w32 = sh_work[v0 + j];
                tt[j] = w32 & 31;
                nd[j] = (w32 >> 5) & 1023;
                int rel = w32 >> 15;
                const float* gr = gi_rel + (size_t)rel * G3 + cc0 + lane;
                r0[j] = __ldg(gr);
                r1[j] = __ldg(gr + 128);
                r2[j] = __ldg(gr + 256);
            }
        }
#pragma unroll
        for (int j = 0; j < 8; j++) {
            if (j < cnt) {
                if (tt[j] != cur_t) {           // warp-uniform branch
                    if (cur_t >= 0) atomicAdd(&sh_acc[cur_t * 32 + lane], acc);
                    acc = 0.f;
                    cur_t = tt[j];
                    gir = sh_gi[(cur_t * 3 + 0) * 32 + lane];
                    giz = sh_gi[(cur_t * 3 + 1) * 32 + lane];
                    gin = sh_gi[(cur_t * 3 + 2) * 32 + lane];
                }
                const uint16_t* gh = sh_gh + nd[j] * 96 + lane;
                const float h  = sh_h[nd[j] * 32 + lane];
                float r = sigmoid_t(gir + r0[j] + bf2f(gh[0]));
                float z = sigmoid_t(giz + r1[j] + bf2f(gh[32]));
                float n = tanh_ap(fmaf(r, bf2f(gh[64]), gin + r2[j]));
                acc += fmaf(z, h - n, n);
            }
        }
    }
    if (cur_t >= 0) atomicAdd(&sh_acc[cur_t * 32 + lane], acc);
    __syncthreads();

    // ---- epilogue: mean + scatter winners ----
    for (int t = warp; t < TOPK; t += 16) {
        const int aim = sh_aim[t];
        if (aim >= 0) {
            const int num = sh_num[t];
            float u = (num > 0) ? sh_acc[t * 32 + lane] / (float)num : 0.f;
            out[((size_t)b * NODES + aim) * HDIM + cc0 + lane] = u;
        }
    }
}

// ---------------------------------------------------------------------------
// Host launcher
// ---------------------------------------------------------------------------
extern "C" void kernel_launch(void* const* d_in, const int* in_sizes, int n_in,
                              void* d_out, int out_size)
{
    const float* node_emb = (const float*)d_in[0];
    const float* ent_tab  = (const float*)d_in[1];
    const float* rel_tab  = (const float*)d_in[2];
    const float* W_ih     = (const float*)d_in[3];
    const float* W_hh     = (const float*)d_in[4];
    const float* b_ih     = (const float*)d_in[5];
    const float* b_hh     = (const float*)d_in[6];
    const int*   aim_nd   = (const int*)d_in[7];
    const int*   aim_ent  = (const int*)d_in[8];
    const int*   nbrs     = (const int*)d_in[9];
    const int*   nb_num   = (const int*)d_in[10];
    float* out = (float*)d_out;

    float *p_gi_rel, *p_gi_ent; uint16_t* p_gh;
    cudaGetSymbolAddress((void**)&p_gi_rel, g_gi_rel);
    cudaGetSymbolAddress((void**)&p_gi_ent, g_gi_ent);
    cudaGetSymbolAddress((void**)&p_gh,     g_gh16);

    cudaFuncSetAttribute(gemm_mma_kernel,
        cudaFuncAttributeMaxDynamicSharedMemorySize, GEMM_SMEM);
    cudaFuncSetAttribute(aggregate_kernel,
        cudaFuncAttributeMaxDynamicSharedMemorySize, AGG_SMEM);

    // 1) fused GEMMs (bf16 tensor cores)
    gemm_mma_kernel<<<882, 256, GEMM_SMEM>>>(
        node_emb, ent_tab, rel_tab, W_ih, W_hh, b_ih, b_hh, aim_ent,
        p_gh, p_gi_ent, p_gi_rel);

    // 2) GRU + masked mean + fused base-copy/dupmask/scatter (balanced)
    aggregate_kernel<<<dim3(4, BB), 512, AGG_SMEM>>>(
        node_emb, p_gi_rel, p_gi_ent, p_gh,
        (const int2*)nbrs, nb_num, aim_nd, out);
}